// round 1
// baseline (speedup 1.0000x reference)
#include <cuda_runtime.h>
#include <cuda_bf16.h>
#include <cstdint>

// Problem constants (fixed shapes per reference):
//   NX=432, NY=496, C=64, B=4, P=40000
// Output: (B, C, NY, NX) float32, row-major -> 54,853,632 elements.
#define NXc 432
#define NYc 496
#define Cc  64
#define Bc  4
#define Pc  40000

// Scratch: cell -> pillar index (-1 = empty).  4*496*432 ints = 3.43 MB.
__device__ int g_idx[Bc * NYc * NXc];
// Coord dtype flag: 1 if voxel_coords is int64, 0 if int32.
__device__ int g_is64;

// ---------------------------------------------------------------------------
// Detect whether coords buffer is int64 or int32.
// Coords are small non-negative ints; if stored as little-endian int64, every
// odd 32-bit word (high half) is zero. For int32 storage the odd words are
// real coordinate values (y0, x1, b1, y2, ...) — all-zero over 300 samples of
// random coords is impossible. Deterministic: same input -> same flag.
// ---------------------------------------------------------------------------
__global__ void detect_dtype_kernel(const int* __restrict__ c32, int n32) {
    if (threadIdx.x == 0 && blockIdx.x == 0) {
        int all_zero = 1;
        int lim = n32 < 600 ? n32 : 600;
        for (int i = 1; i < lim; i += 2) {
            if (c32[i] != 0) { all_zero = 0; break; }
        }
        g_is64 = all_zero;
    }
}

// ---------------------------------------------------------------------------
// Init index grid to -1 (int4 vectorized; 214,272 int4 stores).
// ---------------------------------------------------------------------------
__global__ void init_idx_kernel() {
    unsigned t = blockIdx.x * blockDim.x + threadIdx.x;
    const unsigned n4 = (Bc * NYc * NXc) / 4;
    if (t < n4) {
        reinterpret_cast<int4*>(g_idx)[t] = make_int4(-1, -1, -1, -1);
    }
}

// ---------------------------------------------------------------------------
// Scatter pillar index into the grid: g_idx[b*NY*NX + y*NX + x] = p.
// ---------------------------------------------------------------------------
__global__ void scatter_idx_kernel(const int* __restrict__ c32) {
    int p = blockIdx.x * blockDim.x + threadIdx.x;
    if (p >= Pc) return;
    int x, y, b;
    if (g_is64) {
        const long long* c64 = reinterpret_cast<const long long*>(c32);
        x = (int)c64[p * 3 + 0];
        y = (int)c64[p * 3 + 1];
        b = (int)c64[p * 3 + 2];
    } else {
        x = c32[p * 3 + 0];
        y = c32[p * 3 + 1];
        b = c32[p * 3 + 2];
    }
    g_idx[(b * NYc + y) * NXc + x] = p;
}

// ---------------------------------------------------------------------------
// Gather: every output element written exactly once (no zero-fill pass).
// Thread = one float4 along x. Output layout (B, C, NY, NX):
//   out[((b*C + c)*NY + y)*NX + x]
// Index grid read as int4 (16B-aligned: NX*4 = 1728 bytes, divisible by 16).
// Feature gathers hit L2 (10 MB table, reused 64x across channels).
// Output stores use __stcs (streaming, evict-first) to protect L2 residency
// of g_idx + pillar_features from the 219 MB write stream.
// ---------------------------------------------------------------------------
__global__ void gather_kernel(const float* __restrict__ pf,
                              float* __restrict__ out) {
    const unsigned X4 = NXc / 4;                    // 108
    unsigned t = blockIdx.x * blockDim.x + threadIdx.x;
    const unsigned total = Bc * Cc * NYc * X4;      // 13,713,408
    if (t >= total) return;

    unsigned x4   = t % X4;
    unsigned rest = t / X4;
    unsigned y    = rest % NYc;
    unsigned bc   = rest / NYc;                     // b*64 + c
    unsigned c    = bc & (Cc - 1);
    unsigned b    = bc >> 6;

    int4 iv = *reinterpret_cast<const int4*>(
        g_idx + ((b * NYc + y) * NXc) + x4 * 4);

    float4 o;
    o.x = (iv.x >= 0) ? __ldg(pf + (size_t)iv.x * Cc + c) : 0.0f;
    o.y = (iv.y >= 0) ? __ldg(pf + (size_t)iv.y * Cc + c) : 0.0f;
    o.z = (iv.z >= 0) ? __ldg(pf + (size_t)iv.z * Cc + c) : 0.0f;
    o.w = (iv.w >= 0) ? __ldg(pf + (size_t)iv.w * Cc + c) : 0.0f;

    float4* op = reinterpret_cast<float4*>(
        out + ((size_t)bc * NYc + y) * NXc) + x4;
    __stcs(op, o);
}

extern "C" void kernel_launch(void* const* d_in, const int* in_sizes, int n_in,
                              void* d_out, int out_size) {
    const float* pf  = (const float*)d_in[0];   // pillar_features [P, C] f32
    const int*   c32 = (const int*)d_in[1];     // voxel_coords [P, 3] int32 or int64
    float*       out = (float*)d_out;

    // Number of 32-bit words in the coord buffer (works for either dtype view;
    // in_sizes[1] is the element count per metadata dtype: 120000 either way,
    // so derive a safe lower bound for the detector scan).
    int n32 = in_sizes[1];                      // >= 120000 int32 words exist if int64
    detect_dtype_kernel<<<1, 32>>>(c32, n32);

    const unsigned n4 = (Bc * NYc * NXc) / 4;   // 214,272
    init_idx_kernel<<<(n4 + 255) / 256, 256>>>();

    scatter_idx_kernel<<<(Pc + 255) / 256, 256>>>(c32);

    const unsigned total = Bc * Cc * NYc * (NXc / 4);  // 13,713,408
    gather_kernel<<<(total + 255) / 256, 256>>>(pf, out);
}

// round 2
// speedup vs baseline: 1.2494x; 1.2494x over previous
#include <cuda_runtime.h>
#include <cuda_bf16.h>
#include <cstdint>

// Problem constants (fixed shapes per reference):
//   NX=432, NY=496, C=64, B=4, P=40000
// Output: (B, C, NY, NX) float32, row-major -> 54,853,632 elements.
#define NXc 432
#define NYc 496
#define Cc  64
#define Bc  4
#define Pc  40000

// Scratch: cell -> pillar index (-1 = empty).  4*496*432 ints = 3.43 MB.
__device__ int g_idx[Bc * NYc * NXc];
// Coord dtype flag: 1 if voxel_coords is int64, 0 if int32.
__device__ int g_is64;

// ---------------------------------------------------------------------------
// Detect whether coords buffer is int64 or int32 (see R0 notes). Coords are
// small non-negative ints; little-endian int64 => every odd 32-bit word zero.
// ---------------------------------------------------------------------------
__global__ void detect_dtype_kernel(const int* __restrict__ c32, int n32) {
    if (threadIdx.x == 0 && blockIdx.x == 0) {
        int all_zero = 1;
        int lim = n32 < 600 ? n32 : 600;
        for (int i = 1; i < lim; i += 2) {
            if (c32[i] != 0) { all_zero = 0; break; }
        }
        g_is64 = all_zero;
    }
}

// ---------------------------------------------------------------------------
// Init index grid to -1 (int4 vectorized).
// ---------------------------------------------------------------------------
__global__ void init_idx_kernel() {
    unsigned t = blockIdx.x * blockDim.x + threadIdx.x;
    const unsigned n4 = (Bc * NYc * NXc) / 4;
    if (t < n4) {
        reinterpret_cast<int4*>(g_idx)[t] = make_int4(-1, -1, -1, -1);
    }
}

// ---------------------------------------------------------------------------
// Scatter pillar index into the grid: g_idx[b*NY*NX + y*NX + x] = p.
// ---------------------------------------------------------------------------
__global__ void scatter_idx_kernel(const int* __restrict__ c32) {
    int p = blockIdx.x * blockDim.x + threadIdx.x;
    if (p >= Pc) return;
    int x, y, b;
    if (g_is64) {
        const long long* c64 = reinterpret_cast<const long long*>(c32);
        x = (int)c64[p * 3 + 0];
        y = (int)c64[p * 3 + 1];
        b = (int)c64[p * 3 + 2];
    } else {
        x = c32[p * 3 + 0];
        y = c32[p * 3 + 1];
        b = c32[p * 3 + 2];
    }
    g_idx[(b * NYc + y) * NXc + x] = p;
}

// ---------------------------------------------------------------------------
// Gather v2: thread = (b, y, x4-group, 16-channel chunk).
//   - ONE int4 idx load serves 16 float4 output stores (idx traffic 64x -> 4x)
//   - features loaded as float4 (consecutive channels contiguous in pf),
//     transposed in registers to the NX-contiguous output layout
//   - every output element written exactly once; empty cells write zeros
//   - __stcs streaming stores keep the 219 MB write stream out of L2's way
// ---------------------------------------------------------------------------
__global__ void __launch_bounds__(256) gather_kernel(
        const float* __restrict__ pf, float* __restrict__ out) {
    const unsigned X4 = NXc / 4;                        // 108
    const unsigned total = X4 * NYc * 4 * Bc;           // 857,088 threads
    unsigned t = blockIdx.x * blockDim.x + threadIdx.x;
    if (t >= total) return;

    unsigned x4 = t % X4;
    unsigned r1 = t / X4;
    unsigned y  = r1 % NYc;
    unsigned r2 = r1 / NYc;
    unsigned ck = r2 & 3;                               // channel chunk 0..3
    unsigned b  = r2 >> 2;
    unsigned c0 = ck * 16;

    int4 iv = *reinterpret_cast<const int4*>(
        g_idx + ((b * NYc + y) * NXc) + x4 * 4);

    // Feature row pointers for the 4 cells of this group (channels c0..c0+15).
    const float4* p0 = reinterpret_cast<const float4*>(pf + (long long)iv.x * Cc + c0);
    const float4* p1 = reinterpret_cast<const float4*>(pf + (long long)iv.y * Cc + c0);
    const float4* p2 = reinterpret_cast<const float4*>(pf + (long long)iv.z * Cc + c0);
    const float4* p3 = reinterpret_cast<const float4*>(pf + (long long)iv.w * Cc + c0);

    const size_t chstride = (size_t)NYc * NXc;          // 214,272 floats
    float* ob = out + ((size_t)(b * Cc + c0) * NYc + y) * NXc + x4 * 4;

    const float4 zero = make_float4(0.f, 0.f, 0.f, 0.f);

#pragma unroll
    for (int j = 0; j < 4; j++) {
        float4 f0 = zero, f1 = zero, f2 = zero, f3 = zero;
        if (iv.x >= 0) f0 = __ldg(p0 + j);
        if (iv.y >= 0) f1 = __ldg(p1 + j);
        if (iv.z >= 0) f2 = __ldg(p2 + j);
        if (iv.w >= 0) f3 = __ldg(p3 + j);

        // Transpose: channel c0+4j+m across the 4 x-positions.
        float* o = ob + (size_t)(4 * j) * chstride;
        __stcs(reinterpret_cast<float4*>(o),
               make_float4(f0.x, f1.x, f2.x, f3.x));
        __stcs(reinterpret_cast<float4*>(o + chstride),
               make_float4(f0.y, f1.y, f2.y, f3.y));
        __stcs(reinterpret_cast<float4*>(o + 2 * chstride),
               make_float4(f0.z, f1.z, f2.z, f3.z));
        __stcs(reinterpret_cast<float4*>(o + 3 * chstride),
               make_float4(f0.w, f1.w, f2.w, f3.w));
    }
}

extern "C" void kernel_launch(void* const* d_in, const int* in_sizes, int n_in,
                              void* d_out, int out_size) {
    const float* pf  = (const float*)d_in[0];   // pillar_features [P, C] f32
    const int*   c32 = (const int*)d_in[1];     // voxel_coords [P, 3] int32/int64
    float*       out = (float*)d_out;

    int n32 = in_sizes[1];
    detect_dtype_kernel<<<1, 32>>>(c32, n32);

    const unsigned n4 = (Bc * NYc * NXc) / 4;   // 214,272
    init_idx_kernel<<<(n4 + 255) / 256, 256>>>();

    scatter_idx_kernel<<<(Pc + 255) / 256, 256>>>(c32);

    const unsigned total = (NXc / 4) * NYc * 4 * Bc;    // 857,088
    gather_kernel<<<(total + 255) / 256, 256>>>(pf, out);
}